// round 3
// baseline (speedup 1.0000x reference)
#include <cuda_runtime.h>
#include <mma.h>
using namespace nvcuda;

#define NMAX 50000
#define EMAX 500000
#define BM 128
#define BN 128
#define BK 16

// ---------------- device scratch (static allocations, allowed) --------------
__device__ float g_qkv [(size_t)NMAX * 384];   // Q | K | V per row (stride 384)
__device__ float g_agg [(size_t)NMAX * 128];   // attention output
__device__ float g_buf1[(size_t)NMAX * 128];   // h1 = x + agg@WO + bO (pre-BN1)
__device__ float g_buf2[(size_t)NMAX * 256];   // FFN hidden
__device__ int   g_cnt   [NMAX];
__device__ int   g_rp    [NMAX + 1];
__device__ int   g_cursor[NMAX];
__device__ int   g_srcs  [EMAX];
__device__ int   g_bsum  [256];
__device__ int   g_is64;
__device__ float g_red[512];   // [sum1|sq1|sum2|sq2] x128
__device__ float g_aff[512];   // [sc1|sh1|sc2|sh2]   x128

__device__ __forceinline__ float* bufptr(int id) {
    switch (id) {
        case 0: return g_qkv;
        case 1: return g_agg;
        case 2: return g_buf1;
        case 3: return g_buf2;
    }
    return 0;
}

__device__ __forceinline__ int edge_at(const void* ei, size_t idx) {
    if (g_is64) return (int)((const long long*)ei)[idx];
    return ((const int*)ei)[idx];
}

// ---------------------------- small kernels ---------------------------------
__global__ void k_detect(const void* ei, int e) {
    if (threadIdx.x == 0) {
        const long long* p = (const long long*)ei;
        int m = e < 256 ? e : 256;
        int ok = 1;
        for (int i = 0; i < m; i++) {
            long long v = p[i];
            if (v < 0 || v >= NMAX) { ok = 0; break; }
        }
        g_is64 = ok;
    }
}

__global__ void k_zero(int n) {
    int i = blockIdx.x * blockDim.x + threadIdx.x;
    if (i < n)   g_cnt[i] = 0;
    if (i < 512) g_red[i] = 0.f;
}

__global__ void k_hist(const void* ei, int e) {
    int i = blockIdx.x * blockDim.x + threadIdx.x;
    if (i < e) {
        int d = edge_at(ei, (size_t)e + i);
        atomicAdd(&g_cnt[d], 1);
    }
}

__global__ void k_scan1(int n) {
    __shared__ int sh[1024];
    int t = threadIdx.x;
    int idx = blockIdx.x * 1024 + t;
    int v = (idx < n) ? g_cnt[idx] : 0;
    sh[t] = v;
    __syncthreads();
    for (int off = 1; off < 1024; off <<= 1) {
        int add = (t >= off) ? sh[t - off] : 0;
        __syncthreads();
        sh[t] += add;
        __syncthreads();
    }
    if (idx < n) g_rp[idx] = sh[t] - v;     // exclusive
    if (t == 1023) g_bsum[blockIdx.x] = sh[1023];
}

__global__ void k_scan2(int nb) {
    if (threadIdx.x == 0) {
        int run = 0;
        for (int i = 0; i < nb; i++) { int c = g_bsum[i]; g_bsum[i] = run; run += c; }
    }
}

__global__ void k_scan3(int n, int e) {
    int idx = blockIdx.x * 1024 + threadIdx.x;
    if (idx < n) {
        int v = g_rp[idx] + g_bsum[blockIdx.x];
        g_rp[idx] = v;
        g_cursor[idx] = v;
    }
    if (idx == 0) g_rp[n] = e;
}

__global__ void k_scatter(const void* ei, int e) {
    int i = blockIdx.x * blockDim.x + threadIdx.x;
    if (i < e) {
        int d = edge_at(ei, (size_t)e + i);
        int s = edge_at(ei, (size_t)i);
        int p = atomicAdd(&g_cursor[d], 1);
        g_srcs[p] = s;
    }
}

// ---------------- attention: one warp per destination node ------------------
__global__ void k_attn(int n) {
    int warp = (blockIdx.x * blockDim.x + threadIdx.x) >> 5;
    int lane = threadIdx.x & 31;
    if (warp >= n) return;

    const float* qrow = g_qkv + (size_t)warp * 384 + lane * 4;
    float4 q = *(const float4*)qrow;

    float ax = 0.f, ay = 0.f, az = 0.f, aw = 0.f, se = 0.f;
    int beg = g_rp[warp], end = g_rp[warp + 1];
    for (int p = beg; p < end; ++p) {
        int j = g_srcs[p];
        const float* base = g_qkv + (size_t)j * 384;
        float4 kv = *(const float4*)(base + 128 + lane * 4);
        float4 vv = *(const float4*)(base + 256 + lane * 4);
        float s = q.x * kv.x + q.y * kv.y + q.z * kv.z + q.w * kv.w;
        s += __shfl_xor_sync(0xffffffffu, s, 1);
        s += __shfl_xor_sync(0xffffffffu, s, 2);   // full 16-dim head dot
        s = fminf(fmaxf(s * 0.25f, -5.f), 5.f);    // /sqrt(16), clip
        float e = __expf(s);
        ax += e * vv.x; ay += e * vv.y; az += e * vv.z; aw += e * vv.w;
        se += e;
    }
    float inv = 1.0f / (se + 1e-16f);
    float4 o = make_float4(ax * inv, ay * inv, az * inv, aw * inv);
    *(float4*)(g_agg + (size_t)warp * 128 + lane * 4) = o;
}

// ------------------- tensor-core GEMM (3x tf32 split) ------------------------
// C[:, coff:coff+M] = op( A' @ W + bias + resid' )
// 3-term tf32 split: fp32 accuracy at tensor-core speed.
__global__ __launch_bounds__(256) void tgemm(
    const float* __restrict__ Aext, int Aid,
    const float* __restrict__ W,
    float* __restrict__ Cext, int Cid,
    int nrows, int K, int M, int ldc, int coff,
    const float* __restrict__ bias,
    const float* __restrict__ Rext, int rid, int hasResid, int ldres,
    int ascSlot, int rscSlot, int doRelu)
{
    __shared__ float As[BM][BK + 8];          // 128 x 24
    __shared__ float Ws[BK][BN + 8];          // 16 x 136
    __shared__ float Cs[8][16][16];           // per-warp epilogue scratch

    const float* A = (Aid >= 0) ? bufptr(Aid) : Aext;
    float*       C = (Cid >= 0) ? bufptr(Cid) : Cext;
    const float* resid = hasResid ? ((rid >= 0) ? bufptr(rid) : Rext) : 0;

    int tid  = threadIdx.x;
    int warp = tid >> 5;
    int lane = tid & 31;
    int rowBase = blockIdx.x * BM;
    int colBase = blockIdx.y * BN;

    // warp tile 64x32: warps arranged 2 (row) x 4 (col)
    int wRow = (warp >> 2) * 64;
    int wCol = (warp & 3) * 32;

    wmma::fragment<wmma::accumulator, 16, 16, 8, float> acc[4][2];
#pragma unroll
    for (int i = 0; i < 4; i++)
#pragma unroll
        for (int j = 0; j < 2; j++) wmma::fill_fragment(acc[i][j], 0.f);

    const float* asc = g_aff + (ascSlot >= 0 ? ascSlot : 0) * 128;
    const float* ash = asc + 128;

    for (int k0 = 0; k0 < K; k0 += BK) {
        // stage A tile: 128 x 16 (2 float4 per thread)
#pragma unroll
        for (int u = 0; u < 2; u++) {
            int f4 = tid * 2 + u;               // 0..511
            int r  = f4 >> 2;                   // 0..127
            int c4 = (f4 & 3) * 4;              // 0,4,8,12
            float4 av = make_float4(0.f, 0.f, 0.f, 0.f);
            int arow = rowBase + r;
            if (arow < nrows) {
                av = *(const float4*)(A + (size_t)arow * K + k0 + c4);
                if (ascSlot >= 0) {
                    int kk = k0 + c4;
                    av.x = av.x * asc[kk + 0] + ash[kk + 0];
                    av.y = av.y * asc[kk + 1] + ash[kk + 1];
                    av.z = av.z * asc[kk + 2] + ash[kk + 2];
                    av.w = av.w * asc[kk + 3] + ash[kk + 3];
                }
            }
            *(float4*)(&As[r][c4]) = av;
        }
        // stage W tile: 16 x 128 (2 float4 per thread)
#pragma unroll
        for (int u = 0; u < 2; u++) {
            int f4 = tid * 2 + u;               // 0..511
            int r  = f4 >> 5;                   // 0..15
            int c  = (f4 & 31) * 4;             // 0..124
            float4 wv = *(const float4*)(W + (size_t)(k0 + r) * M + colBase + c);
            *(float4*)(&Ws[r][c]) = wv;
        }
        __syncthreads();

#pragma unroll
        for (int kk = 0; kk < BK; kk += 8) {
            wmma::fragment<wmma::matrix_a, 16, 16, 8, wmma::precision::tf32, wmma::row_major> aHi[4], aLo[4];
            wmma::fragment<wmma::matrix_b, 16, 16, 8, wmma::precision::tf32, wmma::row_major> bHi[2], bLo[2];
#pragma unroll
            for (int mi = 0; mi < 4; mi++) {
                wmma::load_matrix_sync(aHi[mi], &As[wRow + mi * 16][kk], BK + 8);
#pragma unroll
                for (int t = 0; t < aHi[mi].num_elements; t++) {
                    float v = aHi[mi].x[t];
                    float h = wmma::__float_to_tf32(v);
                    aHi[mi].x[t] = h;
                    aLo[mi].x[t] = wmma::__float_to_tf32(v - h);
                }
            }
#pragma unroll
            for (int ni = 0; ni < 2; ni++) {
                wmma::load_matrix_sync(bHi[ni], &Ws[kk][wCol + ni * 16], BN + 8);
#pragma unroll
                for (int t = 0; t < bHi[ni].num_elements; t++) {
                    float v = bHi[ni].x[t];
                    float h = wmma::__float_to_tf32(v);
                    bHi[ni].x[t] = h;
                    bLo[ni].x[t] = wmma::__float_to_tf32(v - h);
                }
            }
#pragma unroll
            for (int mi = 0; mi < 4; mi++)
#pragma unroll
                for (int ni = 0; ni < 2; ni++) {
                    wmma::mma_sync(acc[mi][ni], aHi[mi], bLo[ni], acc[mi][ni]);
                    wmma::mma_sync(acc[mi][ni], aLo[mi], bHi[ni], acc[mi][ni]);
                    wmma::mma_sync(acc[mi][ni], aHi[mi], bHi[ni], acc[mi][ni]);
                }
        }
        __syncthreads();
    }

    // fused epilogue via per-warp smem scratch
#pragma unroll
    for (int mi = 0; mi < 4; mi++)
#pragma unroll
        for (int ni = 0; ni < 2; ni++) {
            wmma::store_matrix_sync(&Cs[warp][0][0], acc[mi][ni], 16, wmma::mem_row_major);
            __syncwarp();
            int r16 = lane >> 1;                 // 0..15
            int c0  = (lane & 1) * 8;            // 0 or 8
            int row = rowBase + wRow + mi * 16 + r16;
            if (row < nrows) {
                int colb = colBase + wCol + ni * 16 + c0;
#pragma unroll
                for (int j = 0; j < 8; j++) {
                    int c = colb + j;
                    float v = Cs[warp][r16][c0 + j];
                    if (bias) v += bias[c];
                    if (resid) {
                        float rr = resid[(size_t)row * ldres + c];
                        if (rscSlot >= 0)
                            rr = rr * g_aff[rscSlot * 128 + c] + g_aff[(rscSlot + 1) * 128 + c];
                        v += rr;
                    }
                    if (doRelu) v = fmaxf(v, 0.f);
                    C[(size_t)row * ldc + coff + c] = v;
                }
            }
            __syncwarp();
        }
}

// ------------------------- batchnorm stats / apply ---------------------------
__global__ void k_stats(int bid, int n, int slot) {
    const float* h = bufptr(bid);
    int c = threadIdx.x;
    float s = 0.f, s2 = 0.f;
    for (int r = blockIdx.x; r < n; r += gridDim.x) {
        float v = h[(size_t)r * 128 + c];
        s += v; s2 += v * v;
    }
    atomicAdd(&g_red[slot * 128 + c], s);
    atomicAdd(&g_red[(slot + 1) * 128 + c], s2);
}

__global__ void k_stats_ext(const float* __restrict__ h, int n, int slot) {
    int c = threadIdx.x;
    float s = 0.f, s2 = 0.f;
    for (int r = blockIdx.x; r < n; r += gridDim.x) {
        float v = h[(size_t)r * 128 + c];
        s += v; s2 += v * v;
    }
    atomicAdd(&g_red[slot * 128 + c], s);
    atomicAdd(&g_red[(slot + 1) * 128 + c], s2);
}

__global__ void k_fin(int slot, const float* __restrict__ gam,
                      const float* __restrict__ bet, int aslot, int n) {
    int c = threadIdx.x;
    float mean = g_red[slot * 128 + c] / (float)n;
    float var  = g_red[(slot + 1) * 128 + c] / (float)n - mean * mean;
    float inv  = rsqrtf(var + 1e-5f);
    float sc   = gam[c] * inv;
    g_aff[aslot * 128 + c]       = sc;
    g_aff[(aslot + 1) * 128 + c] = bet[c] - mean * sc;
}

__global__ void k_apply(float* __restrict__ out, int total) {
    int i = blockIdx.x * blockDim.x + threadIdx.x;
    if (i < total) {
        int c = i & 127;
        out[i] = out[i] * g_aff[256 + c] + g_aff[384 + c];
    }
}

// ------------------------------- launcher ------------------------------------
extern "C" void kernel_launch(void* const* d_in, const int* in_sizes, int n_in,
                              void* d_out, int out_size) {
    const float* x   = (const float*)d_in[0];
    const void*  ei  = d_in[1];
    const float* WQ  = (const float*)d_in[2];
    const float* WK  = (const float*)d_in[3];
    const float* WV  = (const float*)d_in[4];
    const float* WO  = (const float*)d_in[5];
    const float* bO  = (const float*)d_in[6];
    const float* W1  = (const float*)d_in[7];
    const float* b1  = (const float*)d_in[8];
    const float* W2  = (const float*)d_in[9];
    const float* b2  = (const float*)d_in[10];
    const float* g1v = (const float*)d_in[11];
    const float* be1 = (const float*)d_in[12];
    const float* g2v = (const float*)d_in[13];
    const float* be2 = (const float*)d_in[14];

    int n = in_sizes[0] / 128;
    int e = in_sizes[1] / 2;
    float* out = (float*)d_out;

    int nb = (n + 1023) / 1024;

    // CSR build (by destination)
    k_detect <<<1, 32>>>(ei, e);
    k_zero   <<<(n + 255) / 256, 256>>>(n);
    k_hist   <<<(e + 255) / 256, 256>>>(ei, e);
    k_scan1  <<<nb, 1024>>>(n);
    k_scan2  <<<1, 32>>>(nb);
    k_scan3  <<<nb, 1024>>>(n, e);
    k_scatter<<<(e + 255) / 256, 256>>>(ei, e);

    dim3 gemmGrid1((n + 127) / 128, 1);
    dim3 gemmGrid2((n + 127) / 128, 2);

    // QKV projections into interleaved [N,384] buffer (Cid=0 -> g_qkv)
    tgemm<<<gemmGrid1, 256>>>(x, -1, WQ, 0, 0, n, 128, 128, 384, 0,
                              0, 0, -1, 0, 0, -1, -1, 0);
    tgemm<<<gemmGrid1, 256>>>(x, -1, WK, 0, 0, n, 128, 128, 384, 128,
                              0, 0, -1, 0, 0, -1, -1, 0);
    tgemm<<<gemmGrid1, 256>>>(x, -1, WV, 0, 0, n, 128, 128, 384, 256,
                              0, 0, -1, 0, 0, -1, -1, 0);

    // segment softmax attention, warp per node
    k_attn<<<(n + 7) / 8, 256>>>(n);

    // h1 = agg @ WO + bO + x
    tgemm<<<gemmGrid1, 256>>>(0, 1, WO, 0, 2, n, 128, 128, 128, 0,
                              bO, x, -1, 1, 128, -1, -1, 0);

    // BN1 stats -> (scale1, shift1) in g_aff slots 0/1, fused downstream
    k_stats<<<512, 128>>>(2, n, 0);
    k_fin  <<<1, 128>>>(0, g1v, be1, 0, n);

    // hidden = relu( BN1(h1) @ W1 + b1 )
    tgemm<<<gemmGrid2, 256>>>(0, 2, W1, 0, 3, n, 128, 256, 256, 0,
                              b1, 0, -1, 0, 0, 0, -1, 1);

    // h3 = hidden @ W2 + b2 + BN1(h1)  -> d_out (pre-BN2)
    tgemm<<<gemmGrid1, 256>>>(0, 3, W2, out, -1, n, 256, 128, 128, 0,
                              b2, 0, 2, 1, 128, -1, 0, 0);

    // BN2 stats -> apply in place on d_out
    k_stats_ext<<<512, 128>>>(out, n, 2);
    k_fin      <<<1, 128>>>(2, g2v, be2, 2, n);
    k_apply    <<<(n * 128 + 255) / 256, 256>>>(out, n * 128);
}

// round 4
// speedup vs baseline: 1.6327x; 1.6327x over previous
#include <cuda_runtime.h>
#include <cuda_bf16.h>
#include <mma.h>
using namespace nvcuda;

#define NMAX 50000
#define EMAX 500000
#define BM 128
#define BN 128
#define BK 16

// ---------------- device scratch (static allocations, allowed) --------------
__device__ float g_qkv [(size_t)NMAX * 384];   // Q | K | V per row (stride 384)
__device__ float g_agg [(size_t)NMAX * 128];   // attention output
__device__ float g_buf1[(size_t)NMAX * 128];   // h1 = x + agg@WO + bO (pre-BN1)
__device__ float g_buf2[(size_t)NMAX * 256];   // FFN hidden
__device__ float g_wpack[128 * 384];           // WQ|WK|WV packed [k][3*128]
__device__ int   g_cnt   [NMAX];
__device__ int   g_rp    [NMAX + 1];
__device__ int   g_cursor[NMAX];
__device__ int   g_srcs  [EMAX];
__device__ int   g_bsum  [256];
__device__ int   g_is64;
__device__ float g_red[512];   // [sum1|sq1|sum2|sq2] x128
__device__ float g_aff[512];   // [sc1|sh1|sc2|sh2]   x128

__device__ __forceinline__ float* bufptr(int id) {
    switch (id) {
        case 0: return g_qkv;
        case 1: return g_agg;
        case 2: return g_buf1;
        case 3: return g_buf2;
        case 4: return g_wpack;
    }
    return 0;
}

__device__ __forceinline__ int edge_at(const void* ei, size_t idx) {
    if (g_is64) return (int)((const long long*)ei)[idx];
    return ((const int*)ei)[idx];
}

// ---------------------------- small kernels ---------------------------------
__global__ void k_detect(const void* ei, int e) {
    if (threadIdx.x == 0) {
        const long long* p = (const long long*)ei;
        int m = e < 256 ? e : 256;
        int ok = 1;
        for (int i = 0; i < m; i++) {
            long long v = p[i];
            if (v < 0 || v >= NMAX) { ok = 0; break; }
        }
        g_is64 = ok;
    }
}

__global__ void k_pack(const float* __restrict__ WQ, const float* __restrict__ WK,
                       const float* __restrict__ WV) {
    int i = blockIdx.x * 256 + threadIdx.x;
    if (i < 128 * 128) {
        int k = i >> 7, m = i & 127;
        g_wpack[k * 384 + m]       = WQ[i];
        g_wpack[k * 384 + 128 + m] = WK[i];
        g_wpack[k * 384 + 256 + m] = WV[i];
    }
}

__global__ void k_zero(int n) {
    int i = blockIdx.x * blockDim.x + threadIdx.x;
    if (i < n)   g_cnt[i] = 0;
    if (i < 512) g_red[i] = 0.f;
}

__global__ void k_hist(const void* ei, int e) {
    int i = blockIdx.x * blockDim.x + threadIdx.x;
    if (i < e) {
        int d = edge_at(ei, (size_t)e + i);
        atomicAdd(&g_cnt[d], 1);
    }
}

__global__ void k_scan1(int n) {
    __shared__ int sh[1024];
    int t = threadIdx.x;
    int idx = blockIdx.x * 1024 + t;
    int v = (idx < n) ? g_cnt[idx] : 0;
    sh[t] = v;
    __syncthreads();
    for (int off = 1; off < 1024; off <<= 1) {
        int add = (t >= off) ? sh[t - off] : 0;
        __syncthreads();
        sh[t] += add;
        __syncthreads();
    }
    if (idx < n) g_rp[idx] = sh[t] - v;     // exclusive
    if (t == 1023) g_bsum[blockIdx.x] = sh[1023];
}

__global__ void k_scan2(int nb) {
    if (threadIdx.x == 0) {
        int run = 0;
        for (int i = 0; i < nb; i++) { int c = g_bsum[i]; g_bsum[i] = run; run += c; }
    }
}

__global__ void k_scan3(int n, int e) {
    int idx = blockIdx.x * 1024 + threadIdx.x;
    if (idx < n) {
        int v = g_rp[idx] + g_bsum[blockIdx.x];
        g_rp[idx] = v;
        g_cursor[idx] = v;
    }
    if (idx == 0) g_rp[n] = e;
}

__global__ void k_scatter(const void* ei, int e) {
    int i = blockIdx.x * blockDim.x + threadIdx.x;
    if (i < e) {
        int d = edge_at(ei, (size_t)e + i);
        int s = edge_at(ei, (size_t)i);
        int p = atomicAdd(&g_cursor[d], 1);
        g_srcs[p] = s;
    }
}

// ---------------- attention: one warp per destination node ------------------
__global__ void k_attn(int n) {
    int warp = (blockIdx.x * blockDim.x + threadIdx.x) >> 5;
    int lane = threadIdx.x & 31;
    if (warp >= n) return;

    const float* qrow = g_qkv + (size_t)warp * 384 + lane * 4;
    float4 q = *(const float4*)qrow;

    float ax = 0.f, ay = 0.f, az = 0.f, aw = 0.f, se = 0.f;
    int beg = g_rp[warp], end = g_rp[warp + 1];
    for (int p = beg; p < end; ++p) {
        int j = g_srcs[p];
        const float* base = g_qkv + (size_t)j * 384;
        float4 kv = *(const float4*)(base + 128 + lane * 4);
        float4 vv = *(const float4*)(base + 256 + lane * 4);
        float s = q.x * kv.x + q.y * kv.y + q.z * kv.z + q.w * kv.w;
        s += __shfl_xor_sync(0xffffffffu, s, 1);
        s += __shfl_xor_sync(0xffffffffu, s, 2);   // full 16-dim head dot
        s = fminf(fmaxf(s * 0.25f, -5.f), 5.f);    // /sqrt(16), clip
        float e = __expf(s);
        ax += e * vv.x; ay += e * vv.y; az += e * vv.z; aw += e * vv.w;
        se += e;
    }
    float inv = 1.0f / (se + 1e-16f);
    float4 o = make_float4(ax * inv, ay * inv, az * inv, aw * inv);
    *(float4*)(g_agg + (size_t)warp * 128 + lane * 4) = o;
}

// --------------- tensor-core GEMM: bf16 3-term split (m16n16k16) -------------
// C[:, coff:coff+M?] = op( A' @ W + bias + resid' )
// A fp32 -> (hi, lo) bf16 pair in smem; acc += aHi*bHi + aHi*bLo + aLo*bHi.
// Wld = row stride of W; columns used are [colBase, colBase+128).
__global__ __launch_bounds__(256) void tgemm(
    const float* __restrict__ Aext, int Aid,
    const float* __restrict__ W, int Wid, int Wld,
    float* __restrict__ Cext, int Cid,
    int nrows, int K, int ldc, int coff,
    const float* __restrict__ bias,
    const float* __restrict__ Rext, int rid, int hasResid, int ldres,
    int ascSlot, int rscSlot, int doRelu)
{
    __shared__ __nv_bfloat16 AsH[BM][BK + 8];   // 128 x 24 halves
    __shared__ __nv_bfloat16 AsL[BM][BK + 8];
    __shared__ __nv_bfloat16 WsH[BK][BN + 8];   // 16 x 136
    __shared__ __nv_bfloat16 WsL[BK][BN + 8];
    __shared__ float Cs[8][16][16];             // per-warp epilogue scratch

    const float* A = (Aid >= 0) ? bufptr(Aid) : Aext;
    const float* Wp = (Wid >= 0) ? bufptr(Wid) : W;
    float*       C = (Cid >= 0) ? bufptr(Cid) : Cext;
    const float* resid = hasResid ? ((rid >= 0) ? bufptr(rid) : Rext) : 0;

    int tid  = threadIdx.x;
    int warp = tid >> 5;
    int lane = tid & 31;
    int rowBase = blockIdx.x * BM;
    int colBase = blockIdx.y * BN;

    // warp tile 64x32: warps arranged 2 (row) x 4 (col)
    int wRow = (warp >> 2) * 64;
    int wCol = (warp & 3) * 32;

    wmma::fragment<wmma::accumulator, 16, 16, 16, float> acc[4][2];
#pragma unroll
    for (int i = 0; i < 4; i++)
#pragma unroll
        for (int j = 0; j < 2; j++) wmma::fill_fragment(acc[i][j], 0.f);

    const float* asc = g_aff + (ascSlot >= 0 ? ascSlot : 0) * 128;
    const float* ash = asc + 128;

    for (int k0 = 0; k0 < K; k0 += BK) {
        // stage A tile: 128 x 16 fp32 -> hi/lo bf16 (2 float4 per thread)
#pragma unroll
        for (int u = 0; u < 2; u++) {
            int f4 = tid * 2 + u;               // 0..511
            int r  = f4 >> 2;                   // 0..127
            int c4 = (f4 & 3) * 4;              // 0,4,8,12
            float4 av = make_float4(0.f, 0.f, 0.f, 0.f);
            int arow = rowBase + r;
            if (arow < nrows) {
                av = *(const float4*)(A + (size_t)arow * K + k0 + c4);
                if (ascSlot >= 0) {
                    int kk = k0 + c4;
                    av.x = av.x * asc[kk + 0] + ash[kk + 0];
                    av.y = av.y * asc[kk + 1] + ash[kk + 1];
                    av.z = av.z * asc[kk + 2] + ash[kk + 2];
                    av.w = av.w * asc[kk + 3] + ash[kk + 3];
                }
            }
            float vv[4] = {av.x, av.y, av.z, av.w};
#pragma unroll
            for (int j = 0; j < 4; j++) {
                __nv_bfloat16 h = __float2bfloat16(vv[j]);
                AsH[r][c4 + j] = h;
                AsL[r][c4 + j] = __float2bfloat16(vv[j] - __bfloat162float(h));
            }
        }
        // stage W tile: 16 x 128
#pragma unroll
        for (int u = 0; u < 2; u++) {
            int f4 = tid * 2 + u;               // 0..511
            int r  = f4 >> 5;                   // 0..15
            int c  = (f4 & 31) * 4;             // 0..124
            float4 wv = *(const float4*)(Wp + (size_t)(k0 + r) * Wld + colBase + c);
            float vv[4] = {wv.x, wv.y, wv.z, wv.w};
#pragma unroll
            for (int j = 0; j < 4; j++) {
                __nv_bfloat16 h = __float2bfloat16(vv[j]);
                WsH[r][c + j] = h;
                WsL[r][c + j] = __float2bfloat16(vv[j] - __bfloat162float(h));
            }
        }
        __syncthreads();

        wmma::fragment<wmma::matrix_a, 16, 16, 16, __nv_bfloat16, wmma::row_major> aH[4], aL[4];
        wmma::fragment<wmma::matrix_b, 16, 16, 16, __nv_bfloat16, wmma::row_major> bH[2], bL[2];
#pragma unroll
        for (int mi = 0; mi < 4; mi++) {
            wmma::load_matrix_sync(aH[mi], &AsH[wRow + mi * 16][0], BK + 8);
            wmma::load_matrix_sync(aL[mi], &AsL[wRow + mi * 16][0], BK + 8);
        }
#pragma unroll
        for (int ni = 0; ni < 2; ni++) {
            wmma::load_matrix_sync(bH[ni], &WsH[0][wCol + ni * 16], BN + 8);
            wmma::load_matrix_sync(bL[ni], &WsL[0][wCol + ni * 16], BN + 8);
        }
#pragma unroll
        for (int mi = 0; mi < 4; mi++)
#pragma unroll
            for (int ni = 0; ni < 2; ni++) {
                wmma::mma_sync(acc[mi][ni], aH[mi], bL[ni], acc[mi][ni]);
                wmma::mma_sync(acc[mi][ni], aL[mi], bH[ni], acc[mi][ni]);
                wmma::mma_sync(acc[mi][ni], aH[mi], bH[ni], acc[mi][ni]);
            }
        __syncthreads();
    }

    // fused epilogue via per-warp smem scratch
#pragma unroll
    for (int mi = 0; mi < 4; mi++)
#pragma unroll
        for (int ni = 0; ni < 2; ni++) {
            wmma::store_matrix_sync(&Cs[warp][0][0], acc[mi][ni], 16, wmma::mem_row_major);
            __syncwarp();
            int r16 = lane >> 1;                 // 0..15
            int c0  = (lane & 1) * 8;            // 0 or 8
            int row = rowBase + wRow + mi * 16 + r16;
            if (row < nrows) {
                int colb = colBase + wCol + ni * 16 + c0;
#pragma unroll
                for (int j = 0; j < 8; j++) {
                    int c = colb + j;
                    float v = Cs[warp][r16][c0 + j];
                    if (bias) v += bias[c - colBase + coff];
                    if (resid) {
                        float rr = resid[(size_t)row * ldres + c];
                        if (rscSlot >= 0)
                            rr = rr * g_aff[rscSlot * 128 + c] + g_aff[(rscSlot + 1) * 128 + c];
                        v += rr;
                    }
                    if (doRelu) v = fmaxf(v, 0.f);
                    C[(size_t)row * ldc + c] = v;
                }
            }
            __syncwarp();
        }
}

// ------------------------- batchnorm stats / apply ---------------------------
__global__ void k_stats(int bid, int n, int slot) {
    const float* h = bufptr(bid);
    int c = threadIdx.x;
    float s = 0.f, s2 = 0.f;
    for (int r = blockIdx.x; r < n; r += gridDim.x) {
        float v = h[(size_t)r * 128 + c];
        s += v; s2 += v * v;
    }
    atomicAdd(&g_red[slot * 128 + c], s);
    atomicAdd(&g_red[(slot + 1) * 128 + c], s2);
}

__global__ void k_stats_ext(const float* __restrict__ h, int n, int slot) {
    int c = threadIdx.x;
    float s = 0.f, s2 = 0.f;
    for (int r = blockIdx.x; r < n; r += gridDim.x) {
        float v = h[(size_t)r * 128 + c];
        s += v; s2 += v * v;
    }
    atomicAdd(&g_red[slot * 128 + c], s);
    atomicAdd(&g_red[(slot + 1) * 128 + c], s2);
}

__global__ void k_fin(int slot, const float* __restrict__ gam,
                      const float* __restrict__ bet, int aslot, int n) {
    int c = threadIdx.x;
    float mean = g_red[slot * 128 + c] / (float)n;
    float var  = g_red[(slot + 1) * 128 + c] / (float)n - mean * mean;
    float inv  = rsqrtf(var + 1e-5f);
    float sc   = gam[c] * inv;
    g_aff[aslot * 128 + c]       = sc;
    g_aff[(aslot + 1) * 128 + c] = bet[c] - mean * sc;
}

__global__ void k_apply(float* __restrict__ out, int total) {
    int i = blockIdx.x * blockDim.x + threadIdx.x;
    if (i < total) {
        int c = i & 127;
        out[i] = out[i] * g_aff[256 + c] + g_aff[384 + c];
    }
}

// ------------------------------- launcher ------------------------------------
extern "C" void kernel_launch(void* const* d_in, const int* in_sizes, int n_in,
                              void* d_out, int out_size) {
    const float* x   = (const float*)d_in[0];
    const void*  ei  = d_in[1];
    const float* WQ  = (const float*)d_in[2];
    const float* WK  = (const float*)d_in[3];
    const float* WV  = (const float*)d_in[4];
    const float* WO  = (const float*)d_in[5];
    const float* bO  = (const float*)d_in[6];
    const float* W1  = (const float*)d_in[7];
    const float* b1  = (const float*)d_in[8];
    const float* W2  = (const float*)d_in[9];
    const float* b2  = (const float*)d_in[10];
    const float* g1v = (const float*)d_in[11];
    const float* be1 = (const float*)d_in[12];
    const float* g2v = (const float*)d_in[13];
    const float* be2 = (const float*)d_in[14];

    int n = in_sizes[0] / 128;
    int e = in_sizes[1] / 2;
    float* out = (float*)d_out;

    int nb = (n + 1023) / 1024;

    // CSR build (by destination) + weight packing
    k_detect <<<1, 32>>>(ei, e);
    k_pack   <<<64, 256>>>(WQ, WK, WV);
    k_zero   <<<(n + 255) / 256, 256>>>(n);
    k_hist   <<<(e + 255) / 256, 256>>>(ei, e);
    k_scan1  <<<nb, 1024>>>(n);
    k_scan2  <<<1, 32>>>(nb);
    k_scan3  <<<nb, 1024>>>(n, e);
    k_scatter<<<(e + 255) / 256, 256>>>(ei, e);

    dim3 gQKV((n + 127) / 128, 3);
    dim3 g1((n + 127) / 128, 1);
    dim3 g2((n + 127) / 128, 2);

    // QKV: x @ [WQ|WK|WV] -> g_qkv [N,384]  (Wid=4 -> g_wpack, Wld=384)
    tgemm<<<gQKV, 256>>>(x, -1, 0, 4, 384, 0, 0, n, 128, 384, 0,
                         0, 0, -1, 0, 0, -1, -1, 0);

    // segment softmax attention, warp per node
    k_attn<<<(n + 7) / 8, 256>>>(n);

    // h1 = agg @ WO + bO + x
    tgemm<<<g1, 256>>>(0, 1, WO, -1, 128, 0, 2, n, 128, 128, 0,
                       bO, x, -1, 1, 128, -1, -1, 0);

    // BN1 stats -> (scale1, shift1) in g_aff slots 0/1, fused downstream
    k_stats<<<512, 128>>>(2, n, 0);
    k_fin  <<<1, 128>>>(0, g1v, be1, 0, n);

    // hidden = relu( BN1(h1) @ W1 + b1 )
    tgemm<<<g2, 256>>>(0, 2, W1, -1, 256, 0, 3, n, 128, 256, 0,
                       b1, 0, -1, 0, 0, 0, -1, 1);

    // h3 = hidden @ W2 + b2 + BN1(h1)  -> d_out (pre-BN2)
    tgemm<<<g1, 256>>>(0, 3, W2, -1, 128, out, -1, n, 256, 128, 0,
                       b2, 0, 2, 1, 128, -1, 0, 0);

    // BN2 stats -> apply in place on d_out
    k_stats_ext<<<512, 128>>>(out, n, 2);
    k_fin      <<<1, 128>>>(2, g2v, be2, 2, n);
    k_apply    <<<(n * 128 + 255) / 256, 256>>>(out, n * 128);
}